// round 16
// baseline (speedup 1.0000x reference)
#include <cuda_runtime.h>
#include <cuda_fp16.h>
#include <cstdint>

#define N_NODES 50000
#define FDIM    64
#define PER     8
#define E_EDGES 800000
#define NF      (N_NODES * FDIM)

// ---------------- scratch (static __device__ — no allocations) ----------------
__device__ uint32_t g_XH[PER * N_NODES * 32];   // X transposed, fp16 (~51 MB)
__device__ uint32_t g_TH[PER * N_NODES * 32];   // tx1 per period, fp16
__device__ float g_deg[N_NODES];
__device__ __align__(16) int g_cnt[N_NODES];
__device__ int   g_rowptr[N_NODES + 1];
__device__ int   g_cursor[N_NODES];
__device__ volatile int g_bflag[64];
__device__ volatile int g_bagg[64];
__device__ int2  g_edge[E_EDGES];            // {src, weight-as-int}
__device__ unsigned short g_Wh[192 * 128];   // W packed [jphys][k], fp16 (permuted cols)
__device__ float g_bs[192];                  // bx+bh+bg, jphys layout
__device__ float g_wo[64];                   // peephole wc[2], logical f

// ---------------- small helpers ----------------
__device__ __forceinline__ float tanh_fast(float x) {
    float r; asm("tanh.approx.f32 %0, %1;" : "=f"(r) : "f"(x)); return r;
}
__device__ __forceinline__ float fsigmoid(float x) {
    return fmaf(tanh_fast(0.5f * x), 0.5f, 0.5f);
}
__device__ __forceinline__ float ftanh(float x) { return tanh_fast(x); }
__device__ __forceinline__ uint32_t packh2(float a, float b) {
    __half2 h = __floats2half2_rn(a, b);
    return *reinterpret_cast<uint32_t*>(&h);
}

// physical B column jphys -> logical (feature f, gate g3 in {0:i,1:c,2:o})
__device__ __forceinline__ void jmap(int jp, int& f, int& g3) {
    int wn = jp / 48, rem = jp % 48;
    int nt = rem >> 3, r8 = rem & 7, tg = r8 >> 1, e = r8 & 1;
    int slot = nt * 2 + e;
    f  = wn * 16 + tg * 4 + slot / 3;
    g3 = slot % 3;
}

__device__ __forceinline__ void mma_f16(float* c,
                                        uint32_t a0, uint32_t a1, uint32_t a2, uint32_t a3,
                                        uint32_t b0, uint32_t b1) {
    asm volatile(
        "mma.sync.aligned.m16n8k16.row.col.f32.f16.f16.f32 "
        "{%0,%1,%2,%3}, {%4,%5,%6,%7}, {%8,%9}, {%0,%1,%2,%3};"
        : "+f"(c[0]), "+f"(c[1]), "+f"(c[2]), "+f"(c[3])
        : "r"(a0), "r"(a1), "r"(a2), "r"(a3), "r"(b0), "r"(b1));
}
__device__ __forceinline__ void ldsm_x4(uint32_t* r, uint32_t addr) {
    asm volatile("ldmatrix.sync.aligned.m8n8.x4.shared.b16 {%0,%1,%2,%3}, [%4];"
        : "=r"(r[0]), "=r"(r[1]), "=r"(r[2]), "=r"(r[3]) : "r"(addr));
}

// ---------------- K1: zero (counters + scan flags) ----------------
__global__ void zero_kernel() {
    int t = blockIdx.x * blockDim.x + threadIdx.x;
    if (t < N_NODES) { g_deg[t] = 0.0f; g_cnt[t] = 0; }
    if (t < 64) { g_bflag[t] = 0; g_bagg[t] = 0; }
}

// ---------------- K2: fused deg_hist (3125) + transpose (6250) ----------------
#define NB_DH 3125
#define NB_TR 6250
__global__ void dh_tr_kernel(const int* __restrict__ ei, const float* __restrict__ ew,
                             const float* __restrict__ X) {
    int bid = blockIdx.x, tid = threadIdx.x;
    if (bid < NB_DH) {
        int e = bid * 256 + tid;
        if (e < E_EDGES) {
            atomicAdd(&g_deg[ei[e]], ew[e]);
            atomicAdd(&g_cnt[ei[E_EDGES + e]], 1);
        }
    } else {
        // X: [N, F, P] fp32 -> g_XH[p][n][pair] fp16
        int t = (bid - NB_DH) * 256 + tid;   // t < NF/2 = 1.6M exactly
        int n = t >> 5, j = t & 31;
        const float4* src = reinterpret_cast<const float4*>(X + ((size_t)n * 64 + 2 * j) * 8);
        float4 v0 = src[0], v1 = src[1], v2 = src[2], v3 = src[3];
        float f0[8] = {v0.x, v0.y, v0.z, v0.w, v1.x, v1.y, v1.z, v1.w};
        float f1[8] = {v2.x, v2.y, v2.z, v2.w, v3.x, v3.y, v3.z, v3.w};
#pragma unroll
        for (int p = 0; p < PER; p++)
            g_XH[((size_t)p * N_NODES + n) * 32 + j] = packh2(f0[p], f1[p]);
    }
}

// ---------------- K3: single-pass scan, decoupled lookback (49 blocks x 1024) ----
__global__ void scan_kernel() {
    __shared__ int wsum[32];
    __shared__ int spred[49];
    __shared__ int s_off, s_tot;
    int tid = threadIdx.x, lane = tid & 31, wid = tid >> 5, bid = blockIdx.x;
    int i = bid * 1024 + tid;
    int c = (i < N_NODES) ? g_cnt[i] : 0;
    int x = c;
#pragma unroll
    for (int off = 1; off < 32; off <<= 1) {
        int t = __shfl_up_sync(0xffffffffu, x, off);
        if (lane >= off) x += t;
    }
    if (lane == 31) wsum[wid] = x;
    __syncthreads();
    if (wid == 0) {
        int v = wsum[lane];
        int y = v;
#pragma unroll
        for (int off = 1; off < 32; off <<= 1) {
            int t = __shfl_up_sync(0xffffffffu, y, off);
            if (lane >= off) y += t;
        }
        wsum[lane] = y - v;
        if (lane == 31) {
            s_tot = y;
            g_bagg[bid] = y;
            __threadfence();
            g_bflag[bid] = 1;
        }
    }
    __syncthreads();
    // parallel lookback: threads tid < bid each spin on one predecessor
    if (tid < bid) {
        while (g_bflag[tid] == 0) {}
        spred[tid] = g_bagg[tid];
    }
    __syncthreads();
    if (tid == 0) {
        int o = 0;
        for (int b = 0; b < bid; b++) o += spred[b];
        s_off = o;
    }
    __syncthreads();
    int off = s_off;
    if (i < N_NODES) {
        int v = (x - c) + wsum[wid] + off;
        g_rowptr[i] = v;
        g_cursor[i] = v;
    }
    if (bid == 48 && tid == 1023) g_rowptr[N_NODES] = off + s_tot;
}

// ---------------- K4: fused scatter (3125) + pack (97) ----------------
#define NB_SCAT 3125
#define NB_PACK 97
__global__ void scat_pack_kernel(const int* __restrict__ ei, const float* __restrict__ ew,
                                 const float* __restrict__ Wx0, const float* __restrict__ Wx1,
                                 const float* __restrict__ bx, const float* __restrict__ bh,
                                 const float* __restrict__ bg, const float* __restrict__ wc) {
    int bid = blockIdx.x, tid = threadIdx.x;
    if (bid < NB_SCAT) {
        int e = bid * 256 + tid;
        if (e < E_EDGES) {
            int s = ei[e], d = ei[E_EDGES + e];
            float ds = g_deg[s], dd = g_deg[d];
            float is = (ds > 0.0f) ? rsqrtf(fmaxf(ds, 1e-12f)) : 0.0f;
            float id = (dd > 0.0f) ? rsqrtf(fmaxf(dd, 1e-12f)) : 0.0f;
            float w = -is * ew[e] * id;
            int pos = atomicAdd(&g_cursor[d], 1);
            g_edge[pos] = make_int2(s, __float_as_int(w));
        }
    } else {
        int pidx = (bid - NB_SCAT) * 256 + tid;   // < 24832
        if (pidx < 24576) {
            int jp = pidx >> 7, k = pidx & 127;
            int f, g3; jmap(jp, f, g3);
            int gg = (g3 == 0) ? 0 : ((g3 == 1) ? 2 : 3);   // i, c, o
            float v = (k < 64) ? Wx0[gg * 4096 + k * 64 + f]
                               : Wx1[gg * 4096 + (k - 64) * 64 + f];
            __half h = __float2half_rn(v);
            g_Wh[pidx] = *reinterpret_cast<unsigned short*>(&h);
        } else if (pidx < 24576 + 192) {
            int j = pidx - 24576;
            int f, g3; jmap(j, f, g3);
            int gg = (g3 == 0) ? 0 : ((g3 == 1) ? 2 : 3);
            g_bs[j] = bx[gg * 64 + f] + bh[gg * 64 + f] + bg[gg * 64 + f];
        } else if (pidx < 24576 + 192 + 64) {
            int f = pidx - 24768;
            g_wo[f] = wc[2 * 64 + f];
        }
    }
}

// ---------------- K5: pull SpMM, all periods, 2x edge unroll ----------------
__global__ void __launch_bounds__(256) spmm_all_kernel() {
    int warp = (blockIdx.x * blockDim.x + threadIdx.x) >> 5;
    int lane = threadIdx.x & 31;
    if (warp >= N_NODES) return;
    int beg = g_rowptr[warp], end = g_rowptr[warp + 1];
    float ax[PER], ay[PER];
#pragma unroll
    for (int p = 0; p < PER; p++) { ax[p] = 0.0f; ay[p] = 0.0f; }
    int e = beg;
    for (; e + 1 < end; e += 2) {
        int2 e0 = g_edge[e], e1 = g_edge[e + 1];
        float w0 = __int_as_float(e0.y), w1 = __int_as_float(e1.y);
        const uint32_t* b0 = g_XH + (size_t)e0.x * 32 + lane;
        const uint32_t* b1 = g_XH + (size_t)e1.x * 32 + lane;
        uint32_t u0[PER], u1[PER];
#pragma unroll
        for (int p = 0; p < PER; p++) u0[p] = b0[(size_t)p * N_NODES * 32];
#pragma unroll
        for (int p = 0; p < PER; p++) u1[p] = b1[(size_t)p * N_NODES * 32];
#pragma unroll
        for (int p = 0; p < PER; p++) {
            float2 v0 = __half22float2(*reinterpret_cast<__half2*>(&u0[p]));
            float2 v1 = __half22float2(*reinterpret_cast<__half2*>(&u1[p]));
            ax[p] += w0 * v0.x + w1 * v1.x;
            ay[p] += w0 * v0.y + w1 * v1.y;
        }
    }
    if (e < end) {
        int2 e0 = g_edge[e];
        float w0 = __int_as_float(e0.y);
        const uint32_t* b0 = g_XH + (size_t)e0.x * 32 + lane;
#pragma unroll
        for (int p = 0; p < PER; p++) {
            uint32_t u = b0[(size_t)p * N_NODES * 32];
            float2 v = __half22float2(*reinterpret_cast<__half2*>(&u));
            ax[p] += w0 * v.x;
            ay[p] += w0 * v.y;
        }
    }
#pragma unroll
    for (int p = 0; p < PER; p++)
        g_TH[((size_t)p * N_NODES + warp) * 32 + lane] = packh2(ax[p], ay[p]);
}

// ---------------- K6: fused mma.sync GEMM, ldmatrix fragments ----------------
#define ASTRIDE 272
#define BSTRIDE 272
#define SM_A    0
#define SM_B    34816
#define SMEM_BYTES (34816 + 52224)

__global__ void __launch_bounds__(256, 1) gemm_fused(float* __restrict__ out) {
    extern __shared__ char smem[];
    int tid = threadIdx.x;
    int wid = tid >> 5, lane = tid & 31;
    int g = lane >> 2, tg = lane & 3;
    int wm = wid & 1;          // warp row: 0/1 -> rows 0-63 / 64-127
    int wn = wid >> 1;         // warp col: 0..3 -> jphys base 48*wn
    int r0 = blockIdx.x * 128;

    // ---- B copy (once): [192][128] fp16, 3072 uint4 ----
    for (int it = tid; it < 3072; it += 256) {
        int j = it >> 4, c = it & 15;
        *(uint4*)(smem + SM_B + j * BSTRIDE + c * 16) = ((const uint4*)g_Wh)[j * 16 + c];
    }

    // ---- per-thread biases ----
    float bsv[12], wov[4];
#pragma unroll
    for (int s = 0; s < 12; s++) {
        int nt = s >> 1, e = s & 1;
        bsv[s] = g_bs[wn * 48 + nt * 8 + tg * 2 + e];
    }
#pragma unroll
    for (int t = 0; t < 4; t++) wov[t] = g_wo[wn * 16 + tg * 4 + t];

    float accO[4][2][4];
#pragma unroll
    for (int mt = 0; mt < 4; mt++)
#pragma unroll
        for (int h = 0; h < 2; h++)
#pragma unroll
            for (int t = 0; t < 4; t++) accO[mt][h][t] = 0.0f;

    // ldmatrix per-lane addresses
    uint32_t smA = (uint32_t)__cvta_generic_to_shared(smem + SM_A);
    uint32_t smB = (uint32_t)__cvta_generic_to_shared(smem + SM_B);
    int lrow = lane & 15, khalf = lane >> 4;
    uint32_t aaddr[4];
#pragma unroll
    for (int mt = 0; mt < 4; mt++)
        aaddr[mt] = smA + (wm * 64 + mt * 16 + lrow) * ASTRIDE + khalf * 16;
    // B x4 over nt-pairs: lane>>3 selects matrix m; m>>1 -> nt within pair, m&1 -> k-half
    int bm = lane >> 3;
    int bnt = (bm >> 1) * 8 + (lane & 7);
    int bk16 = bm & 1;
    uint32_t baddr[3];
#pragma unroll
    for (int np = 0; np < 3; np++)
        baddr[np] = smB + (wn * 48 + np * 16 + bnt) * BSTRIDE + bk16 * 16;

    // copyA pieces: A row = 256B = 16 uint4 (cc<8: X fp16, cc>=8: tx1 fp16)
    int cc = tid & 15, rb = tid >> 4;   // rows rb + 16*i, i<8
    char* dst0 = smem + SM_A + cc * 16;
    int idx4 = (cc < 8) ? cc : (cc - 8);

    // ---- initial A copy (p = 0) ----
    {
        const uint32_t* srcbase = (cc < 8) ? g_XH : g_TH;
#pragma unroll
        for (int i = 0; i < 8; i++) {
            int r = rb + i * 16;
            int gr = r0 + r;
            uint4 u = make_uint4(0, 0, 0, 0);
            if (gr < N_NODES)
                u = ((const uint4*)(srcbase + (size_t)gr * 32))[idx4];
            *(uint4*)(dst0 + r * ASTRIDE) = u;
        }
    }

    for (int p = 0; p < PER; p++) {
        __syncthreads();   // A(p) visible

        float acc[4][6][4];
#pragma unroll
        for (int mt = 0; mt < 4; mt++)
#pragma unroll
            for (int nt = 0; nt < 6; nt++)
#pragma unroll
                for (int q = 0; q < 4; q++) acc[mt][nt][q] = 0.0f;

#pragma unroll
        for (int ks = 0; ks < 8; ks++) {
            uint32_t a[4][4];
#pragma unroll
            for (int mt = 0; mt < 4; mt++)
                ldsm_x4(a[mt], aaddr[mt] + ks * 32);
#pragma unroll
            for (int np = 0; np < 3; np++) {
                uint32_t b[4];
                ldsm_x4(b, baddr[np] + ks * 32);
#pragma unroll
                for (int mt = 0; mt < 4; mt++) {
                    mma_f16(acc[mt][2 * np],     a[mt][0], a[mt][1], a[mt][2], a[mt][3], b[0], b[1]);
                    mma_f16(acc[mt][2 * np + 1], a[mt][0], a[mt][1], a[mt][2], a[mt][3], b[2], b[3]);
                }
            }
        }
        __syncthreads();   // A reads done; safe to overwrite A

        // ---- prefetch A(p+1) into regs, thread-local epilogue, store ----
        bool more = (p + 1 < PER);
        uint4 u[8];
        if (more) {
            const uint32_t* srcbase = ((cc < 8) ? g_XH : g_TH)
                                    + (size_t)(p + 1) * N_NODES * 32;
#pragma unroll
            for (int i = 0; i < 8; i++) {
                int gr = r0 + rb + i * 16;
                u[i] = (gr < N_NODES) ? ((const uint4*)(srcbase + (size_t)gr * 32))[idx4]
                                      : make_uint4(0, 0, 0, 0);
            }
        }
#pragma unroll
        for (int mt = 0; mt < 4; mt++)
#pragma unroll
            for (int h = 0; h < 2; h++)
#pragma unroll
                for (int t = 0; t < 4; t++) {
                    int s0 = 3 * t, s1 = 3 * t + 1, s2 = 3 * t + 2;
                    float gi = acc[mt][s0 >> 1][h * 2 + (s0 & 1)] + bsv[s0];
                    float gc = acc[mt][s1 >> 1][h * 2 + (s1 & 1)] + bsv[s1];
                    float go = acc[mt][s2 >> 1][h * 2 + (s2 & 1)] + bsv[s2];
                    float I  = fsigmoid(gi);
                    float T  = ftanh(gc);
                    float Cn = I * T;
                    float O  = fsigmoid(go + wov[t] * Cn);
                    accO[mt][h][t] += O * ftanh(Cn);
                }
        if (more) {
#pragma unroll
            for (int i = 0; i < 8; i++)
                *(uint4*)(dst0 + (rb + i * 16) * ASTRIDE) = u[i];
        }
    }

    // ---- final output write (write-only, no RMW) ----
#pragma unroll
    for (int mt = 0; mt < 4; mt++)
#pragma unroll
        for (int h = 0; h < 2; h++) {
            int row = r0 + wm * 64 + mt * 16 + g + h * 8;
            if (row < N_NODES) {
                *(float4*)(out + (size_t)row * 64 + wn * 16 + tg * 4) =
                    make_float4(accO[mt][h][0], accO[mt][h][1],
                                accO[mt][h][2], accO[mt][h][3]);
            }
        }
}

// ---------------- launch ----------------
extern "C" void kernel_launch(void* const* d_in, const int* in_sizes, int n_in,
                              void* d_out, int out_size) {
    const float* X   = (const float*)d_in[0];
    const int*   ei  = (const int*)d_in[1];
    const float* ew  = (const float*)d_in[2];
    const float* Wx0 = (const float*)d_in[3];
    const float* Wx1 = (const float*)d_in[4];
    const float* bx  = (const float*)d_in[5];
    // d_in[6]=Wh0, d_in[7]=Wh1 unused (H=0 -> cheb(H)=bh)
    const float* bh  = (const float*)d_in[8];
    const float* wc  = (const float*)d_in[9];
    const float* bg  = (const float*)d_in[10];
    float* out = (float*)d_out;

    cudaFuncSetAttribute(gemm_fused, cudaFuncAttributeMaxDynamicSharedMemorySize, SMEM_BYTES);

    zero_kernel<<<(N_NODES + 255) / 256, 256>>>();                             // 1
    dh_tr_kernel<<<NB_DH + NB_TR, 256>>>(ei, ew, X);                           // 2
    scan_kernel<<<49, 1024>>>();                                               // 3
    scat_pack_kernel<<<NB_SCAT + NB_PACK, 256>>>(ei, ew, Wx0, Wx1, bx, bh, bg, wc); // 4
    spmm_all_kernel<<<(N_NODES * 32 + 255) / 256, 256>>>();                    // 5
    gemm_fused<<<(N_NODES + 127) / 128, 256, SMEM_BYTES>>>(out);               // 6
}

// round 17
// speedup vs baseline: 1.0782x; 1.0782x over previous
#include <cuda_runtime.h>
#include <cuda_fp16.h>
#include <cstdint>

#define N_NODES 50000
#define FDIM    64
#define PER     8
#define E_EDGES 800000
#define NF      (N_NODES * FDIM)

// ---------------- scratch (static __device__ — no allocations) ----------------
// NOTE: zero-initialized at module load; gemm_fused tail re-zeroes g_cnt/g_deg
// so every kernel_launch sequence starts from zeroed counters (replay-safe).
__device__ uint32_t g_XH[PER * N_NODES * 32];   // X transposed, fp16 (~51 MB)
__device__ uint32_t g_TH[PER * N_NODES * 32];   // tx1 per period, fp16
__device__ float g_deg[N_NODES];
__device__ __align__(16) int g_cnt[N_NODES];
__device__ int   g_rowptr[N_NODES + 1];
__device__ int   g_cursor[N_NODES];
__device__ int   g_btot[49];
__device__ int   g_esrc[E_EDGES];
__device__ float g_ewn[E_EDGES];
__device__ unsigned short g_Wh[192 * 128];   // W packed [jphys][k], fp16 (permuted cols)
__device__ float g_bs[192];                  // bx+bh+bg, jphys layout
__device__ float g_wo[64];                   // peephole wc[2], logical f

// ---------------- small helpers ----------------
__device__ __forceinline__ float tanh_fast(float x) {
    float r; asm("tanh.approx.f32 %0, %1;" : "=f"(r) : "f"(x)); return r;
}
__device__ __forceinline__ float fsigmoid(float x) {
    return fmaf(tanh_fast(0.5f * x), 0.5f, 0.5f);
}
__device__ __forceinline__ float ftanh(float x) { return tanh_fast(x); }
__device__ __forceinline__ uint32_t packh2(float a, float b) {
    __half2 h = __floats2half2_rn(a, b);
    return *reinterpret_cast<uint32_t*>(&h);
}

// physical B column jphys -> logical (feature f, gate g3 in {0:i,1:c,2:o})
__device__ __forceinline__ void jmap(int jp, int& f, int& g3) {
    int wn = jp / 48, rem = jp % 48;
    int nt = rem >> 3, r8 = rem & 7, tg = r8 >> 1, e = r8 & 1;
    int slot = nt * 2 + e;
    f  = wn * 16 + tg * 4 + slot / 3;
    g3 = slot % 3;
}

__device__ __forceinline__ void mma_f16(float* c,
                                        uint32_t a0, uint32_t a1, uint32_t a2, uint32_t a3,
                                        uint32_t b0, uint32_t b1) {
    asm volatile(
        "mma.sync.aligned.m16n8k16.row.col.f32.f16.f16.f32 "
        "{%0,%1,%2,%3}, {%4,%5,%6,%7}, {%8,%9}, {%0,%1,%2,%3};"
        : "+f"(c[0]), "+f"(c[1]), "+f"(c[2]), "+f"(c[3])
        : "r"(a0), "r"(a1), "r"(a2), "r"(a3), "r"(b0), "r"(b1));
}
__device__ __forceinline__ void ldsm_x4(uint32_t* r, uint32_t addr) {
    asm volatile("ldmatrix.sync.aligned.m8n8.x4.shared.b16 {%0,%1,%2,%3}, [%4];"
        : "=r"(r[0]), "=r"(r[1]), "=r"(r[2]), "=r"(r[3]) : "r"(addr));
}
__device__ __forceinline__ void ldsm_x2(uint32_t& r0, uint32_t& r1, uint32_t addr) {
    asm volatile("ldmatrix.sync.aligned.m8n8.x2.shared.b16 {%0,%1}, [%2];"
        : "=r"(r0), "=r"(r1) : "r"(addr));
}

// ---------------- K1: degree + dst histogram ----------------
__global__ void deg_hist_kernel(const int* __restrict__ ei, const float* __restrict__ ew) {
    int e = blockIdx.x * blockDim.x + threadIdx.x;
    if (e >= E_EDGES) return;
    atomicAdd(&g_deg[ei[e]], ew[e]);
    atomicAdd(&g_cnt[ei[E_EDGES + e]], 1);
}

// ---------------- K2: block-local scan (49 blocks x 1024) ----------------
__global__ void scan1_kernel() {
    __shared__ int wsum[32];
    int tid = threadIdx.x, lane = tid & 31, wid = tid >> 5;
    int i = blockIdx.x * 1024 + tid;
    int c = (i < N_NODES) ? g_cnt[i] : 0;
    int x = c;
#pragma unroll
    for (int off = 1; off < 32; off <<= 1) {
        int t = __shfl_up_sync(0xffffffffu, x, off);
        if (lane >= off) x += t;
    }
    if (lane == 31) wsum[wid] = x;
    __syncthreads();
    if (wid == 0) {
        int v = wsum[lane];
        int y = v;
#pragma unroll
        for (int off = 1; off < 32; off <<= 1) {
            int t = __shfl_up_sync(0xffffffffu, y, off);
            if (lane >= off) y += t;
        }
        wsum[lane] = y - v;
        if (lane == 31) g_btot[blockIdx.x] = y;
    }
    __syncthreads();
    if (i < N_NODES) g_rowptr[i] = (x - c) + wsum[wid];
}

// ---------------- K3: add block offsets (196 blocks x 256) ----------------
__global__ void scan2_kernel() {
    int bid = blockIdx.x, tid = threadIdx.x;
    int grp = bid >> 2;                 // 4 blocks per 1024-node group
    int off = 0;
    for (int b = 0; b < grp; b++) off += g_btot[b];
    int i = bid * 256 + tid;
    if (i < N_NODES) {
        int v = g_rowptr[i] + off;
        g_rowptr[i] = v;
        g_cursor[i] = v;
    }
    if (bid == 195 && tid == 0) {
        int tot = 0;
        for (int b = 0; b < 49; b++) tot += g_btot[b];
        g_rowptr[N_NODES] = tot;
    }
}

// ---------------- K4: fused scatter (3125) + transpose (6250) + pack (97) ----------------
#define NB_SCAT 3125
#define NB_TRAN 6250
#define NB_PACK 97
__global__ void fused_mid_kernel(const int* __restrict__ ei, const float* __restrict__ ew,
                                 const float* __restrict__ X,
                                 const float* __restrict__ Wx0, const float* __restrict__ Wx1,
                                 const float* __restrict__ bx, const float* __restrict__ bh,
                                 const float* __restrict__ bg, const float* __restrict__ wc) {
    int bid = blockIdx.x, tid = threadIdx.x;
    if (bid < NB_SCAT) {
        // edge scatter into CSR (needs g_deg + g_cursor)
        int e = bid * 256 + tid;
        if (e < E_EDGES) {
            int s = ei[e], d = ei[E_EDGES + e];
            float ds = g_deg[s], dd = g_deg[d];
            float is = (ds > 0.0f) ? rsqrtf(fmaxf(ds, 1e-12f)) : 0.0f;
            float id = (dd > 0.0f) ? rsqrtf(fmaxf(dd, 1e-12f)) : 0.0f;
            float w = -is * ew[e] * id;
            int pos = atomicAdd(&g_cursor[d], 1);
            g_esrc[pos] = s;
            g_ewn[pos] = w;
        }
    } else if (bid < NB_SCAT + NB_TRAN) {
        // X: [N, F, P] fp32 -> g_XH[p][n][pair] fp16
        int t = (bid - NB_SCAT) * 256 + tid;   // t < NF/2 = 1.6M exactly
        int n = t >> 5, j = t & 31;
        const float4* src = reinterpret_cast<const float4*>(X + ((size_t)n * 64 + 2 * j) * 8);
        float4 v0 = src[0], v1 = src[1], v2 = src[2], v3 = src[3];
        float f0[8] = {v0.x, v0.y, v0.z, v0.w, v1.x, v1.y, v1.z, v1.w};
        float f1[8] = {v2.x, v2.y, v2.z, v2.w, v3.x, v3.y, v3.z, v3.w};
#pragma unroll
        for (int p = 0; p < PER; p++)
            g_XH[((size_t)p * N_NODES + n) * 32 + j] = packh2(f0[p], f1[p]);
    } else {
        int pidx = (bid - NB_SCAT - NB_TRAN) * 256 + tid;   // < 24832
        if (pidx < 24576) {
            int jp = pidx >> 7, k = pidx & 127;
            int f, g3; jmap(jp, f, g3);
            int gg = (g3 == 0) ? 0 : ((g3 == 1) ? 2 : 3);   // i, c, o
            float v = (k < 64) ? Wx0[gg * 4096 + k * 64 + f]
                               : Wx1[gg * 4096 + (k - 64) * 64 + f];
            __half h = __float2half_rn(v);
            g_Wh[pidx] = *reinterpret_cast<unsigned short*>(&h);
        } else if (pidx < 24576 + 192) {
            int j = pidx - 24576;
            int f, g3; jmap(j, f, g3);
            int gg = (g3 == 0) ? 0 : ((g3 == 1) ? 2 : 3);
            g_bs[j] = bx[gg * 64 + f] + bh[gg * 64 + f] + bg[gg * 64 + f];
        } else if (pidx < 24576 + 192 + 64) {
            int f = pidx - 24768;
            g_wo[f] = wc[2 * 64 + f];
        }
    }
}

// ---------------- K5: pull SpMM, all periods ----------------
__global__ void __launch_bounds__(256) spmm_all_kernel() {
    int warp = (blockIdx.x * blockDim.x + threadIdx.x) >> 5;
    int lane = threadIdx.x & 31;
    if (warp >= N_NODES) return;
    int beg = g_rowptr[warp], end = g_rowptr[warp + 1];
    float ax[PER], ay[PER];
#pragma unroll
    for (int p = 0; p < PER; p++) { ax[p] = 0.0f; ay[p] = 0.0f; }
    for (int e = beg; e < end; e++) {
        int s = g_esrc[e];
        float w = g_ewn[e];
        const uint32_t* base = g_XH + (size_t)s * 32 + lane;
        uint32_t u[PER];
#pragma unroll
        for (int p = 0; p < PER; p++) u[p] = base[(size_t)p * N_NODES * 32];
#pragma unroll
        for (int p = 0; p < PER; p++) {
            float2 v = __half22float2(*reinterpret_cast<__half2*>(&u[p]));
            ax[p] += w * v.x;
            ay[p] += w * v.y;
        }
    }
#pragma unroll
    for (int p = 0; p < PER; p++)
        g_TH[((size_t)p * N_NODES + warp) * 32 + lane] = packh2(ax[p], ay[p]);
}

// ---------------- K6: fused mma.sync GEMM, ldmatrix fragments ----------------
#define ASTRIDE 272
#define BSTRIDE 272
#define SM_A    0
#define SM_B    34816
#define SMEM_BYTES (34816 + 52224)

__global__ void __launch_bounds__(256, 1) gemm_fused(float* __restrict__ out) {
    extern __shared__ char smem[];
    int tid = threadIdx.x;
    int wid = tid >> 5, lane = tid & 31;
    int g = lane >> 2, tg = lane & 3;
    int wm = wid & 1;          // warp row: 0/1 -> rows 0-63 / 64-127
    int wn = wid >> 1;         // warp col: 0..3 -> jphys base 48*wn
    int r0 = blockIdx.x * 128;

    // ---- B copy (once): [192][128] fp16, 3072 uint4 ----
    for (int it = tid; it < 3072; it += 256) {
        int j = it >> 4, c = it & 15;
        *(uint4*)(smem + SM_B + j * BSTRIDE + c * 16) = ((const uint4*)g_Wh)[j * 16 + c];
    }

    // ---- per-thread biases ----
    float bsv[12], wov[4];
#pragma unroll
    for (int s = 0; s < 12; s++) {
        int nt = s >> 1, e = s & 1;
        bsv[s] = g_bs[wn * 48 + nt * 8 + tg * 2 + e];
    }
#pragma unroll
    for (int t = 0; t < 4; t++) wov[t] = g_wo[wn * 16 + tg * 4 + t];

    float accO[4][2][4];
#pragma unroll
    for (int mt = 0; mt < 4; mt++)
#pragma unroll
        for (int h = 0; h < 2; h++)
#pragma unroll
            for (int t = 0; t < 4; t++) accO[mt][h][t] = 0.0f;

    // ldmatrix per-lane addresses
    uint32_t smA = (uint32_t)__cvta_generic_to_shared(smem + SM_A);
    uint32_t smB = (uint32_t)__cvta_generic_to_shared(smem + SM_B);
    int lrow = lane & 15, khalf = lane >> 4;
    uint32_t aaddr[4];
#pragma unroll
    for (int mt = 0; mt < 4; mt++)
        aaddr[mt] = smA + (wm * 64 + mt * 16 + lrow) * ASTRIDE + khalf * 16;
    int brow = lane & 7, bk = (lane >> 3) & 1;
    uint32_t baddr[6];
#pragma unroll
    for (int nt = 0; nt < 6; nt++)
        baddr[nt] = smB + (wn * 48 + nt * 8 + brow) * BSTRIDE + bk * 16;

    // copyA pieces: A row = 256B = 16 uint4 (cc<8: X fp16, cc>=8: tx1 fp16)
    int cc = tid & 15, rb = tid >> 4;   // rows rb + 16*i, i<8
    char* dst0 = smem + SM_A + cc * 16;
    int idx4 = (cc < 8) ? cc : (cc - 8);

    // ---- initial A copy (p = 0) ----
    {
        const uint32_t* srcbase = (cc < 8) ? g_XH : g_TH;
#pragma unroll
        for (int i = 0; i < 8; i++) {
            int r = rb + i * 16;
            int gr = r0 + r;
            uint4 u = make_uint4(0, 0, 0, 0);
            if (gr < N_NODES)
                u = ((const uint4*)(srcbase + (size_t)gr * 32))[idx4];
            *(uint4*)(dst0 + r * ASTRIDE) = u;
        }
    }

    for (int p = 0; p < PER; p++) {
        __syncthreads();   // A(p) visible

        float acc[4][6][4];
#pragma unroll
        for (int mt = 0; mt < 4; mt++)
#pragma unroll
            for (int nt = 0; nt < 6; nt++)
#pragma unroll
                for (int q = 0; q < 4; q++) acc[mt][nt][q] = 0.0f;

#pragma unroll
        for (int ks = 0; ks < 8; ks++) {
            uint32_t a[4][4];
#pragma unroll
            for (int mt = 0; mt < 4; mt++)
                ldsm_x4(a[mt], aaddr[mt] + ks * 32);
#pragma unroll
            for (int nt = 0; nt < 6; nt++) {
                uint32_t b0, b1;
                ldsm_x2(b0, b1, baddr[nt] + ks * 32);
#pragma unroll
                for (int mt = 0; mt < 4; mt++)
                    mma_f16(acc[mt][nt], a[mt][0], a[mt][1], a[mt][2], a[mt][3], b0, b1);
            }
        }
        __syncthreads();   // A reads done; safe to overwrite A

        // ---- prefetch A(p+1) into regs, thread-local epilogue, store ----
        bool more = (p + 1 < PER);
        uint4 u[8];
        if (more) {
            const uint32_t* srcbase = ((cc < 8) ? g_XH : g_TH)
                                    + (size_t)(p + 1) * N_NODES * 32;
#pragma unroll
            for (int i = 0; i < 8; i++) {
                int gr = r0 + rb + i * 16;
                u[i] = (gr < N_NODES) ? ((const uint4*)(srcbase + (size_t)gr * 32))[idx4]
                                      : make_uint4(0, 0, 0, 0);
            }
        }
#pragma unroll
        for (int mt = 0; mt < 4; mt++)
#pragma unroll
            for (int h = 0; h < 2; h++)
#pragma unroll
                for (int t = 0; t < 4; t++) {
                    int s0 = 3 * t, s1 = 3 * t + 1, s2 = 3 * t + 2;
                    float gi = acc[mt][s0 >> 1][h * 2 + (s0 & 1)] + bsv[s0];
                    float gc = acc[mt][s1 >> 1][h * 2 + (s1 & 1)] + bsv[s1];
                    float go = acc[mt][s2 >> 1][h * 2 + (s2 & 1)] + bsv[s2];
                    float I  = fsigmoid(gi);
                    float T  = ftanh(gc);
                    float Cn = I * T;
                    float O  = fsigmoid(go + wov[t] * Cn);
                    accO[mt][h][t] += O * ftanh(Cn);
                }
        if (more) {
#pragma unroll
            for (int i = 0; i < 8; i++)
                *(uint4*)(dst0 + (rb + i * 16) * ASTRIDE) = u[i];
        }
    }

    // ---- final output write (write-only, no RMW) ----
#pragma unroll
    for (int mt = 0; mt < 4; mt++)
#pragma unroll
        for (int h = 0; h < 2; h++) {
            int row = r0 + wm * 64 + mt * 16 + g + h * 8;
            if (row < N_NODES) {
                *(float4*)(out + (size_t)row * 64 + wn * 16 + tg * 4) =
                    make_float4(accO[mt][h][0], accO[mt][h][1],
                                accO[mt][h][2], accO[mt][h][3]);
            }
        }

    // ---- tail: re-zero counters for next replay (g_cnt/g_deg dead by now) ----
    if (blockIdx.x < 196) {
        int i = blockIdx.x * 256 + tid;
        if (i < N_NODES) { g_deg[i] = 0.0f; g_cnt[i] = 0; }
    }
}

// ---------------- launch ----------------
extern "C" void kernel_launch(void* const* d_in, const int* in_sizes, int n_in,
                              void* d_out, int out_size) {
    const float* X   = (const float*)d_in[0];
    const int*   ei  = (const int*)d_in[1];
    const float* ew  = (const float*)d_in[2];
    const float* Wx0 = (const float*)d_in[3];
    const float* Wx1 = (const float*)d_in[4];
    const float* bx  = (const float*)d_in[5];
    // d_in[6]=Wh0, d_in[7]=Wh1 unused (H=0 -> cheb(H)=bh)
    const float* bh  = (const float*)d_in[8];
    const float* wc  = (const float*)d_in[9];
    const float* bg  = (const float*)d_in[10];
    float* out = (float*)d_out;

    cudaFuncSetAttribute(gemm_fused, cudaFuncAttributeMaxDynamicSharedMemorySize, SMEM_BYTES);

    deg_hist_kernel<<<(E_EDGES + 255) / 256, 256>>>(ei, ew);                   // 1
    scan1_kernel<<<49, 1024>>>();                                              // 2
    scan2_kernel<<<196, 256>>>();                                              // 3
    fused_mid_kernel<<<NB_SCAT + NB_TRAN + NB_PACK, 256>>>(                    // 4
        ei, ew, X, Wx0, Wx1, bx, bh, bg, wc);
    spmm_all_kernel<<<(N_NODES * 32 + 255) / 256, 256>>>();                    // 5
    gemm_fused<<<(N_NODES + 127) / 128, 256, SMEM_BYTES>>>(out);               // 6
}